// round 1
// baseline (speedup 1.0000x reference)
#include <cuda_runtime.h>
#include <cstdint>

// Fan-model nonlinear mixing:
//   out[b,x] = L + (L^2 - Q)/2
//   L = sum_p E[b,p]   * a[p,x]
//   Q = sum_p E[b,p]^2 * a[p,x]^2
// (exact identity for the strict-upper-triangle pairwise bilinear term)
//
// E: (224, 12)  A: (12, 512*512)  out: (224, 512*512), all fp32.

#define NPIX (512 * 512)
#define NP   12
#define NB   224
#define NPAIRS (NPIX / 2)   // 131072 pixel-pairs (f32x2 packed)

__global__ __launch_bounds__(256) void fm_mix_kernel(
    const float* __restrict__ E,
    const float* __restrict__ A,
    float* __restrict__ out)
{
    // smem: per (band,p) a float4 {e, e, -e^2, -e^2} so a single LDS.128
    // yields both packed operands, Q accumulates negated (no neg needed).
    __shared__ float4 sF[NB * NP];   // 224*12*16 = 43008 B
    for (int i = threadIdx.x; i < NB * NP; i += blockDim.x) {
        float e = E[i];
        sF[i] = make_float4(e, e, -e * e, -e * e);
    }
    __syncthreads();

    uint32_t sbase;
    asm("{ .reg .u64 t; cvta.to.shared.u64 t, %1; cvt.u32.u64 %0, t; }"
        : "=r"(sbase) : "l"(sF));

    const int x2 = blockIdx.x * blockDim.x + threadIdx.x;  // pixel-pair index
    if (x2 >= NPAIRS) return;

    // Load a[p] (2 adjacent pixels, packed) and compute a^2 once; reused
    // across all 224 bands -> A read from DRAM exactly once.
    unsigned long long a[NP], a2[NP];
#pragma unroll
    for (int p = 0; p < NP; p++) {
        a[p] = ((const unsigned long long*)(A + (size_t)p * NPIX))[x2];
        asm("mul.rn.f32x2 %0, %1, %2;" : "=l"(a2[p]) : "l"(a[p]), "l"(a[p]));
    }

    const unsigned long long HALF2 = 0x3F0000003F000000ULL;  // {0.5f, 0.5f}
    unsigned long long* o = (unsigned long long*)out;

#pragma unroll 2
    for (int b = 0; b < NB; b++) {
        unsigned long long L = 0ULL;   // {0.f, 0.f}
        unsigned long long Qn = 0ULL;  // accumulates -Q
        const uint32_t addr = sbase + (uint32_t)b * (NP * 16);
#pragma unroll
        for (int p = 0; p < NP; p++) {
            unsigned long long ee, ne2;
            asm("ld.shared.v2.u64 {%0, %1}, [%2];"
                : "=l"(ee), "=l"(ne2) : "r"(addr + p * 16));
            asm("fma.rn.f32x2 %0, %1, %2, %3;"
                : "=l"(L) : "l"(a[p]), "l"(ee), "l"(L));
            asm("fma.rn.f32x2 %0, %1, %2, %3;"
                : "=l"(Qn) : "l"(a2[p]), "l"(ne2), "l"(Qn));
        }
        // nl = L*L - Q ; res = 0.5*nl + L
        unsigned long long nl, res;
        asm("fma.rn.f32x2 %0, %1, %1, %2;" : "=l"(nl) : "l"(L), "l"(Qn));
        asm("fma.rn.f32x2 %0, %1, %2, %3;"
            : "=l"(res) : "l"(nl), "l"(HALF2), "l"(L));
        o[(size_t)b * (NPIX / 2) + x2] = res;
    }
}

extern "C" void kernel_launch(void* const* d_in, const int* in_sizes, int n_in,
                              void* d_out, int out_size)
{
    // E has 224*12 = 2688 elements, A has 12*512*512 = 3145728. Select by size
    // so we're robust to metadata ordering.
    const float* E = (const float*)d_in[0];
    const float* A = (const float*)d_in[1];
    if (in_sizes[0] > in_sizes[1]) {
        E = (const float*)d_in[1];
        A = (const float*)d_in[0];
    }
    float* out = (float*)d_out;

    const int threads = 256;
    const int blocks = NPAIRS / threads;  // 512
    fm_mix_kernel<<<blocks, threads>>>(E, A, out);
}

// round 3
// speedup vs baseline: 1.3621x; 1.3621x over previous
#include <cuda_runtime.h>
#include <cstdint>

// Fan-model nonlinear mixing:
//   out[b,x] = L + (L^2 - Q)/2
//   L = sum_p E[b,p]   * a[p,x]
//   Q = sum_p E[b,p]^2 * a[p,x]^2
// E: (224, 12)  A: (12, 512*512)  out: (224, 512*512), all fp32.
//
// R3: same as R2 (4 px/thread, f32x2 FMA, STG.128) with the band-stride
// bug fixed: out viewed as u64* has NPIX/2 elements per band, not NPIX/4.

#define NPIX (512 * 512)
#define NP   12
#define NB   224

__global__ __launch_bounds__(128, 4) void fm_mix_kernel(
    const float* __restrict__ E,
    const float* __restrict__ A,
    float* __restrict__ out)
{
    // Per (band,p): {e, e, -e^2, -e^2} so one LDS.128 feeds both packed
    // operands; Q accumulates negated.
    __shared__ float4 sF[NB * NP];   // 43008 B
    for (int i = threadIdx.x; i < NB * NP; i += blockDim.x) {
        float e = E[i];
        sF[i] = make_float4(e, e, -e * e, -e * e);
    }
    __syncthreads();

    uint32_t sbase;
    asm("{ .reg .u64 t; cvta.to.shared.u64 t, %1; cvt.u32.u64 %0, t; }"
        : "=r"(sbase) : "l"(sF));

    const int t = blockIdx.x * blockDim.x + threadIdx.x;  // 4-pixel group id
    // grid sized exactly: 65536 threads * 4 px = NPIX, no bounds check

    // Load a[p] for 4 adjacent pixels (one LDG.128 per p), square once.
    unsigned long long a01[NP], a23[NP], s01[NP], s23[NP];
#pragma unroll
    for (int p = 0; p < NP; p++) {
        const ulonglong2 v =
            ((const ulonglong2*)(A + (size_t)p * NPIX))[t];
        a01[p] = v.x;
        a23[p] = v.y;
        asm("mul.rn.f32x2 %0, %1, %2;" : "=l"(s01[p]) : "l"(v.x), "l"(v.x));
        asm("mul.rn.f32x2 %0, %1, %2;" : "=l"(s23[p]) : "l"(v.y), "l"(v.y));
    }

    const unsigned long long HALF2 = 0x3F0000003F000000ULL;  // {0.5f, 0.5f}
    // out as u64 (2 px per element): this thread's 4 px start at 2*t;
    // each band advances NPIX/2 u64 elements.
    unsigned long long* obase = (unsigned long long*)out + 2 * (size_t)t;

#pragma unroll 2
    for (int b = 0; b < NB; b++) {
        unsigned long long L01 = 0ULL, Q01 = 0ULL;  // Q accumulates -Q
        unsigned long long L23 = 0ULL, Q23 = 0ULL;
        const uint32_t addr = sbase + (uint32_t)b * (NP * 16);
#pragma unroll
        for (int p = 0; p < NP; p++) {
            unsigned long long ee, ne2;
            asm("ld.shared.v2.u64 {%0, %1}, [%2];"
                : "=l"(ee), "=l"(ne2) : "r"(addr + p * 16));
            asm("fma.rn.f32x2 %0, %1, %2, %3;"
                : "=l"(L01) : "l"(a01[p]), "l"(ee), "l"(L01));
            asm("fma.rn.f32x2 %0, %1, %2, %3;"
                : "=l"(Q01) : "l"(s01[p]), "l"(ne2), "l"(Q01));
            asm("fma.rn.f32x2 %0, %1, %2, %3;"
                : "=l"(L23) : "l"(a23[p]), "l"(ee), "l"(L23));
            asm("fma.rn.f32x2 %0, %1, %2, %3;"
                : "=l"(Q23) : "l"(s23[p]), "l"(ne2), "l"(Q23));
        }
        // res = L + 0.5*(L*L - Q)
        unsigned long long n01, n23, r01, r23;
        asm("fma.rn.f32x2 %0, %1, %1, %2;" : "=l"(n01) : "l"(L01), "l"(Q01));
        asm("fma.rn.f32x2 %0, %1, %1, %2;" : "=l"(n23) : "l"(L23), "l"(Q23));
        asm("fma.rn.f32x2 %0, %1, %2, %3;"
            : "=l"(r01) : "l"(n01), "l"(HALF2), "l"(L01));
        asm("fma.rn.f32x2 %0, %1, %2, %3;"
            : "=l"(r23) : "l"(n23), "l"(HALF2), "l"(L23));
        // streaming 16B store (4 pixels); band stride = NPIX/2 u64
        asm volatile("st.global.cs.v2.u64 [%0], {%1, %2};"
                     :: "l"(obase + (size_t)b * (NPIX / 2)),
                        "l"(r01), "l"(r23) : "memory");
    }
}

extern "C" void kernel_launch(void* const* d_in, const int* in_sizes, int n_in,
                              void* d_out, int out_size)
{
    const float* E = (const float*)d_in[0];
    const float* A = (const float*)d_in[1];
    if (in_sizes[0] > in_sizes[1]) {
        E = (const float*)d_in[1];
        A = (const float*)d_in[0];
    }
    float* out = (float*)d_out;

    const int threads = 128;
    const int blocks = (NPIX / 4) / threads;  // 512
    fm_mix_kernel<<<blocks, threads>>>(E, A, out);
}

// round 4
// speedup vs baseline: 1.4325x; 1.0517x over previous
#include <cuda_runtime.h>
#include <cstdint>

// Fan-model nonlinear mixing:
//   out[b,x] = L + (L^2 - Q)/2
//   L = sum_p E[b,p]   * a[p,x]
//   Q = sum_p E[b,p]^2 * a[p,x]^2
// E: (224, 12)  A: (12, 512*512)  out: (224, 512*512), all fp32.
//
// R4: 8 pixels per thread (four f32x2 lane-pairs). The per-band shared
// E-table LDS stream (R3 binder, L1=57%) is amortized over 2x the pixels;
// FMA work/px unchanged. ~220 regs, 2 CTAs/SM.

#define NPIX (512 * 512)
#define NP   12
#define NB   224

__global__ __launch_bounds__(128, 2) void fm_mix_kernel(
    const float* __restrict__ E,
    const float* __restrict__ A,
    float* __restrict__ out)
{
    // Per (band,p): {e, e, -e^2, -e^2}; one LDS.128 feeds both packed
    // operands, Q accumulates negated.
    __shared__ float4 sF[NB * NP];   // 43008 B
    for (int i = threadIdx.x; i < NB * NP; i += blockDim.x) {
        float e = E[i];
        sF[i] = make_float4(e, e, -e * e, -e * e);
    }
    __syncthreads();

    uint32_t sbase;
    asm("{ .reg .u64 t; cvta.to.shared.u64 t, %1; cvt.u32.u64 %0, t; }"
        : "=r"(sbase) : "l"(sF));

    const int t = blockIdx.x * blockDim.x + threadIdx.x;  // 8-pixel group id
    // grid: 256 blocks * 128 thr * 8 px = NPIX exactly, no bounds check

    // Load a[p] for 8 adjacent pixels (two LDG.128 per p), square once.
    unsigned long long a0[NP], a1[NP], a2[NP], a3[NP];
    unsigned long long s0[NP], s1[NP], s2[NP], s3[NP];
#pragma unroll
    for (int p = 0; p < NP; p++) {
        const ulonglong2* row = (const ulonglong2*)(A + (size_t)p * NPIX);
        const ulonglong2 v0 = row[2 * t];
        const ulonglong2 v1 = row[2 * t + 1];
        a0[p] = v0.x; a1[p] = v0.y; a2[p] = v1.x; a3[p] = v1.y;
        asm("mul.rn.f32x2 %0, %1, %2;" : "=l"(s0[p]) : "l"(v0.x), "l"(v0.x));
        asm("mul.rn.f32x2 %0, %1, %2;" : "=l"(s1[p]) : "l"(v0.y), "l"(v0.y));
        asm("mul.rn.f32x2 %0, %1, %2;" : "=l"(s2[p]) : "l"(v1.x), "l"(v1.x));
        asm("mul.rn.f32x2 %0, %1, %2;" : "=l"(s3[p]) : "l"(v1.y), "l"(v1.y));
    }

    const unsigned long long HALF2 = 0x3F0000003F000000ULL;  // {0.5f, 0.5f}
    // out as u64 (2 px/elem): thread's 8 px start at 4*t; band stride NPIX/2.
    unsigned long long* obase = (unsigned long long*)out + 4 * (size_t)t;

#pragma unroll 1
    for (int b = 0; b < NB; b++) {
        unsigned long long L0 = 0ULL, Q0 = 0ULL;  // Q accumulates -Q
        unsigned long long L1 = 0ULL, Q1 = 0ULL;
        unsigned long long L2 = 0ULL, Q2 = 0ULL;
        unsigned long long L3 = 0ULL, Q3 = 0ULL;
        const uint32_t addr = sbase + (uint32_t)b * (NP * 16);
#pragma unroll
        for (int p = 0; p < NP; p++) {
            unsigned long long ee, ne2;
            asm("ld.shared.v2.u64 {%0, %1}, [%2];"
                : "=l"(ee), "=l"(ne2) : "r"(addr + p * 16));
            asm("fma.rn.f32x2 %0, %1, %2, %3;" : "=l"(L0) : "l"(a0[p]), "l"(ee),  "l"(L0));
            asm("fma.rn.f32x2 %0, %1, %2, %3;" : "=l"(Q0) : "l"(s0[p]), "l"(ne2), "l"(Q0));
            asm("fma.rn.f32x2 %0, %1, %2, %3;" : "=l"(L1) : "l"(a1[p]), "l"(ee),  "l"(L1));
            asm("fma.rn.f32x2 %0, %1, %2, %3;" : "=l"(Q1) : "l"(s1[p]), "l"(ne2), "l"(Q1));
            asm("fma.rn.f32x2 %0, %1, %2, %3;" : "=l"(L2) : "l"(a2[p]), "l"(ee),  "l"(L2));
            asm("fma.rn.f32x2 %0, %1, %2, %3;" : "=l"(Q2) : "l"(s2[p]), "l"(ne2), "l"(Q2));
            asm("fma.rn.f32x2 %0, %1, %2, %3;" : "=l"(L3) : "l"(a3[p]), "l"(ee),  "l"(L3));
            asm("fma.rn.f32x2 %0, %1, %2, %3;" : "=l"(Q3) : "l"(s3[p]), "l"(ne2), "l"(Q3));
        }
        // res = L + 0.5*(L*L - Q)
        unsigned long long n0, n1, n2, n3, r0, r1, r2, r3;
        asm("fma.rn.f32x2 %0, %1, %1, %2;" : "=l"(n0) : "l"(L0), "l"(Q0));
        asm("fma.rn.f32x2 %0, %1, %1, %2;" : "=l"(n1) : "l"(L1), "l"(Q1));
        asm("fma.rn.f32x2 %0, %1, %1, %2;" : "=l"(n2) : "l"(L2), "l"(Q2));
        asm("fma.rn.f32x2 %0, %1, %1, %2;" : "=l"(n3) : "l"(L3), "l"(Q3));
        asm("fma.rn.f32x2 %0, %1, %2, %3;" : "=l"(r0) : "l"(n0), "l"(HALF2), "l"(L0));
        asm("fma.rn.f32x2 %0, %1, %2, %3;" : "=l"(r1) : "l"(n1), "l"(HALF2), "l"(L1));
        asm("fma.rn.f32x2 %0, %1, %2, %3;" : "=l"(r2) : "l"(n2), "l"(HALF2), "l"(L2));
        asm("fma.rn.f32x2 %0, %1, %2, %3;" : "=l"(r3) : "l"(n3), "l"(HALF2), "l"(L3));

        unsigned long long* ob = obase + (size_t)b * (NPIX / 2);
        asm volatile("st.global.cs.v2.u64 [%0], {%1, %2};"
                     :: "l"(ob), "l"(r0), "l"(r1) : "memory");
        asm volatile("st.global.cs.v2.u64 [%0], {%1, %2};"
                     :: "l"(ob + 2), "l"(r2), "l"(r3) : "memory");
    }
}

extern "C" void kernel_launch(void* const* d_in, const int* in_sizes, int n_in,
                              void* d_out, int out_size)
{
    const float* E = (const float*)d_in[0];
    const float* A = (const float*)d_in[1];
    if (in_sizes[0] > in_sizes[1]) {
        E = (const float*)d_in[1];
        A = (const float*)d_in[0];
    }
    float* out = (float*)d_out;

    const int threads = 128;
    const int blocks = (NPIX / 8) / threads;  // 256
    fm_mix_kernel<<<blocks, threads>>>(E, A, out);
}